// round 1
// baseline (speedup 1.0000x reference)
#include <cuda_runtime.h>

#define CC    512
#define HIDN  128
#define HWN   3136
#define NT    64
#define KT    64
#define LDA   68   // As row stride (floats), 68*4=272B -> 16B aligned rows
#define LDB   68
#define LDH   68
#define EPSV  1e-5f

// Fused: per-batch branch select -> GEMM1 (W1 @ x) -> BN+ReLU (in SMEM) -> GEMM2 (W2 @ h)
// One CTA handles (batch b, 64-pixel tile). 256 threads, 8x4 register tile per thread.
__global__ __launch_bounds__(256, 2)
void msp_fused(const float* __restrict__ x, const int* __restrict__ mod,
               const float* __restrict__ w1_rgb, const float* __restrict__ rm_rgb,
               const float* __restrict__ rv_rgb, const float* __restrict__ g_rgb,
               const float* __restrict__ b_rgb,  const float* __restrict__ w2_rgb,
               const float* __restrict__ w1_inf, const float* __restrict__ rm_inf,
               const float* __restrict__ rv_inf, const float* __restrict__ g_inf,
               const float* __restrict__ b_inf,  const float* __restrict__ w2_inf,
               float* __restrict__ out)
{
    extern __shared__ float smem[];
    float* As     = smem;                    // [128][LDA]  W1 k-chunk, reused for W2 chunks
    float* Bs     = As + HIDN * LDA;         // [KT][LDB]   x chunk
    float* hs     = Bs + KT * LDB;           // [HIDN][LDH] hidden activations (post BN+ReLU)
    float* sscale = hs + HIDN * LDH;         // [128]
    float* sshift = sscale + HIDN;           // [128]

    const int b   = blockIdx.y;
    const int p0  = blockIdx.x * NT;
    const int tid = threadIdx.x;
    const int mi  = tid >> 4, ni = tid & 15;
    const int m0  = mi * 8,   n0 = ni * 4;

    const bool rgb = (mod[b] == 1);
    const float* w1 = rgb ? w1_rgb : w1_inf;
    const float* w2 = rgb ? w2_rgb : w2_inf;
    const float* rm = rgb ? rm_rgb : rm_inf;
    const float* rv = rgb ? rv_rgb : rv_inf;
    const float* gg = rgb ? g_rgb  : g_inf;
    const float* bb = rgb ? b_rgb  : b_inf;

    // BN folded scale/shift (ordered before first use by the first __syncthreads below)
    if (tid < HIDN) {
        float s = gg[tid] * rsqrtf(rv[tid] + EPSV);
        sscale[tid] = s;
        sshift[tid] = bb[tid] - rm[tid] * s;
    }

    const float* xb = x + ((size_t)b * CC) * HWN + p0;

    float acc[8][4];
    #pragma unroll
    for (int i = 0; i < 8; i++)
        #pragma unroll
        for (int j = 0; j < 4; j++) acc[i][j] = 0.f;

    // ---------------- GEMM1: h[128,64] = W1[128,512] @ x[512,64] ----------------
    for (int k0 = 0; k0 < CC; k0 += KT) {
        // stage W1 chunk: As[m][k] = w1[m][k0+k]   (128 rows x 16 float4)
        #pragma unroll
        for (int t = 0; t < 8; t++) {
            int idx = tid + t * 256;            // 0..2047
            int r = idx >> 4, c4 = (idx & 15) << 2;
            float4 v = *(const float4*)&w1[r * CC + k0 + c4];
            *(float4*)&As[r * LDA + c4] = v;
        }
        // stage x chunk: Bs[k][n] = x[b][k0+k][p0+n]   (64 rows x 16 float4)
        #pragma unroll
        for (int t = 0; t < 4; t++) {
            int idx = tid + t * 256;            // 0..1023
            int r = idx >> 4, c4 = (idx & 15) << 2;
            float4 v = *(const float4*)&xb[(size_t)(k0 + r) * HWN + c4];
            *(float4*)&Bs[r * LDB + c4] = v;
        }
        __syncthreads();

        #pragma unroll 4
        for (int k = 0; k < KT; k++) {
            float4 bv = *(const float4*)&Bs[k * LDB + n0];
            float a[8];
            #pragma unroll
            for (int i = 0; i < 8; i++) a[i] = As[(m0 + i) * LDA + k];
            #pragma unroll
            for (int i = 0; i < 8; i++) {
                acc[i][0] = fmaf(a[i], bv.x, acc[i][0]);
                acc[i][1] = fmaf(a[i], bv.y, acc[i][1]);
                acc[i][2] = fmaf(a[i], bv.z, acc[i][2]);
                acc[i][3] = fmaf(a[i], bv.w, acc[i][3]);
            }
        }
        __syncthreads();
    }

    // BN + ReLU epilogue -> hs (stays in SMEM, never touches HBM)
    #pragma unroll
    for (int i = 0; i < 8; i++) {
        int m = m0 + i;
        float s = sscale[m], sh = sshift[m];
        float4 v;
        v.x = fmaxf(fmaf(acc[i][0], s, sh), 0.f);
        v.y = fmaxf(fmaf(acc[i][1], s, sh), 0.f);
        v.z = fmaxf(fmaf(acc[i][2], s, sh), 0.f);
        v.w = fmaxf(fmaf(acc[i][3], s, sh), 0.f);
        *(float4*)&hs[m * LDH + n0] = v;
    }
    __syncthreads();

    // ---------------- GEMM2: out[512,64] = W2[512,128] @ hs[128,64] ----------------
    float* outb = out + ((size_t)b * CC) * HWN + p0;
    for (int chunk = 0; chunk < 4; chunk++) {
        #pragma unroll
        for (int i = 0; i < 8; i++)
            #pragma unroll
            for (int j = 0; j < 4; j++) acc[i][j] = 0.f;

        for (int kc = 0; kc < HIDN; kc += KT) {
            // stage W2 chunk into As: As[r][c] = w2[chunk*128+r][kc+c]
            #pragma unroll
            for (int t = 0; t < 8; t++) {
                int idx = tid + t * 256;
                int r = idx >> 4, c4 = (idx & 15) << 2;
                float4 v = *(const float4*)&w2[(chunk * HIDN + r) * HIDN + kc + c4];
                *(float4*)&As[r * LDA + c4] = v;
            }
            __syncthreads();

            #pragma unroll 4
            for (int k = 0; k < KT; k++) {
                float4 bv = *(const float4*)&hs[(kc + k) * LDH + n0];
                float a[8];
                #pragma unroll
                for (int i = 0; i < 8; i++) a[i] = As[(m0 + i) * LDA + k];
                #pragma unroll
                for (int i = 0; i < 8; i++) {
                    acc[i][0] = fmaf(a[i], bv.x, acc[i][0]);
                    acc[i][1] = fmaf(a[i], bv.y, acc[i][1]);
                    acc[i][2] = fmaf(a[i], bv.z, acc[i][2]);
                    acc[i][3] = fmaf(a[i], bv.w, acc[i][3]);
                }
            }
            __syncthreads();
        }

        #pragma unroll
        for (int i = 0; i < 8; i++) {
            float4 v = make_float4(acc[i][0], acc[i][1], acc[i][2], acc[i][3]);
            *(float4*)&outb[(size_t)(chunk * HIDN + m0 + i) * HWN + n0] = v;
        }
    }
}

extern "C" void kernel_launch(void* const* d_in, const int* in_sizes, int n_in,
                              void* d_out, int out_size)
{
    const float* x      = (const float*)d_in[0];
    const int*   mod    = (const int*)  d_in[1];
    const float* w1_rgb = (const float*)d_in[2];
    const float* rm_rgb = (const float*)d_in[3];
    const float* rv_rgb = (const float*)d_in[4];
    const float* g_rgb  = (const float*)d_in[5];
    const float* b_rgb  = (const float*)d_in[6];
    const float* w2_rgb = (const float*)d_in[7];
    const float* w1_inf = (const float*)d_in[8];
    const float* rm_inf = (const float*)d_in[9];
    const float* rv_inf = (const float*)d_in[10];
    const float* g_inf  = (const float*)d_in[11];
    const float* b_inf  = (const float*)d_in[12];
    const float* w2_inf = (const float*)d_in[13];
    float* out = (float*)d_out;

    const int B = in_sizes[1];  // mod has one entry per batch element

    const size_t smem_bytes = (size_t)(HIDN * LDA + KT * LDB + HIDN * LDH + 2 * HIDN) * sizeof(float);
    cudaFuncSetAttribute(msp_fused, cudaFuncAttributeMaxDynamicSharedMemorySize, (int)smem_bytes);

    dim3 grid(HWN / NT, B);
    msp_fused<<<grid, 256, smem_bytes>>>(
        x, mod,
        w1_rgb, rm_rgb, rv_rgb, g_rgb, b_rgb, w2_rgb,
        w1_inf, rm_inf, rv_inf, g_inf, b_inf, w2_inf,
        out);
}